// round 13
// baseline (speedup 1.0000x reference)
#include <cuda_runtime.h>
#include <cuda_fp16.h>
#include <math.h>
#include <stdint.h>

#define B_  512
#define S_  200
#define H_  256
#define K_  16
#define ROWS (B_*S_)          // 102400
#define TM  128               // rows per CTA (kernel 1)
#define NBLK (ROWS/TM)        // 800 (max tiles; ~half exit early)

// ---- kernel-1 smem layout (words) ----
#define ASTW  132
#define CBSTW 36
#define A_WORDS  (128*ASTW)
#define BC_OFF   A_WORDS
#define BC_ONE   (256*CBSTW)
#define W3_OFF   (BC_OFF + 2*BC_ONE)
#define W3STW 132
#define RID_OFF  (W3_OFF + 16*W3STW)
#define SM_WORDS (RID_OFF + 128)
#define SM_BYTES (SM_WORDS*4)             // 150272

// ---- kernel-2 smem layout (words): one CTA per batch, ALL X resident ----
#define XCH    64                         // s-rows per X chunk
#define XSTW2  132                        // X chunk row stride (words)
#define XBUF2  (XCH*XSTW2)                // 8448
#define DS2_OFF (4*XBUF2)                 // 33792 ; Ds: 16 k x 256 s fp16
#define DST2   132
#define AFST   17                         // Af row stride - conflict-free
#define AF2_OFF (DS2_OFF + 16*DST2)       // 35904
#define TF2_OFF (AF2_OFF + S_*AFST)       // 39304
#define IK2_OFF (TF2_OFF + S_)            // 39504
#define K2_WORDS (IK2_OFF + 16)           // 39520
#define K2_BYTES (K2_WORDS*4)             // 158080 (occupancy 1)

// scratch
__device__ float    g_A[ROWS * K_];          // masked K-softmax logits
__device__ uint32_t g_Xh[(ROWS + 56) * 128]; // X fp16 [row][h]; dead rows stay 0
__device__ uint32_t g_Wh[2 * 32768];         // W1,W2 fp16 [l][c4][n256][kl64]
__device__ uint32_t g_Wh3[16 * 128];         // W3 fp16 [n16][k256]
__device__ int      g_rows[ROWS];            // compacted unmasked row ids
__device__ int      g_cnt;                   // number of unmasked rows

__device__ __forceinline__ uint32_t smem_u32(const void* p) {
    uint32_t a;
    asm("{ .reg .u64 t; cvta.to.shared.u64 t, %1; cvt.u32.u64 %0, t; }"
        : "=r"(a) : "l"(p));
    return a;
}
__device__ __forceinline__ uint32_t pack_h2(float lo, float hi) {
    const __half2 h = __floats2half2_rn(lo, hi);
    return *(const uint32_t*)&h;
}
__device__ __forceinline__ void mma16(float c[4], const uint32_t a[4],
                                      uint32_t b0, uint32_t b1) {
    asm("mma.sync.aligned.m16n8k16.row.col.f32.f16.f16.f32 "
        "{%0,%1,%2,%3}, {%4,%5,%6,%7}, {%8,%9}, {%0,%1,%2,%3};"
        : "+f"(c[0]), "+f"(c[1]), "+f"(c[2]), "+f"(c[3])
        : "r"(a[0]), "r"(a[1]), "r"(a[2]), "r"(a[3]), "r"(b0), "r"(b1));
}
__device__ __forceinline__ void ldsm_x4(uint32_t& r0, uint32_t& r1,
                                        uint32_t& r2, uint32_t& r3, uint32_t addr) {
    asm volatile("ldmatrix.sync.aligned.m8n8.x4.shared.b16 {%0,%1,%2,%3}, [%4];"
                 : "=r"(r0), "=r"(r1), "=r"(r2), "=r"(r3) : "r"(addr));
}
__device__ __forceinline__ void ldsm_x4_t(uint32_t& r0, uint32_t& r1,
                                          uint32_t& r2, uint32_t& r3, uint32_t addr) {
    asm volatile("ldmatrix.sync.aligned.m8n8.x4.trans.shared.b16 {%0,%1,%2,%3}, [%4];"
                 : "=r"(r0), "=r"(r1), "=r"(r2), "=r"(r3) : "r"(addr));
}
__device__ __forceinline__ void cpasync16(uint32_t dst, const void* src) {
    asm volatile("cp.async.cg.shared.global [%0], [%1], 16;" :: "r"(dst), "l"(src));
}
#define CP_COMMIT() asm volatile("cp.async.commit_group;" ::: "memory")
#define CP_WAIT0()  asm volatile("cp.async.wait_group 0;" ::: "memory")

// ---------------------------------------------------------------------------
// Prep: blocks 0-65 convert weights; blocks 66-465 compact unmasked rows
// ---------------------------------------------------------------------------
__global__ void prep_kernel(const float* __restrict__ W1,
                            const float* __restrict__ W2,
                            const float* __restrict__ W3,
                            const int*   __restrict__ mask)
{
    const int tid = threadIdx.x;
    if (blockIdx.x < 66) {
        const int i = blockIdx.x * 256 + tid;
        if (i < 16384) {
            const int kl8 = i & 7;
            const int n   = (i >> 3) & 255;
            const int c   = (i >> 11) & 3;
            const int l   = i >> 13;
            const float* W = l ? W2 : W1;
            const int kbase = c * 64 + kl8 * 8;
            uint4 o;
            o.x = pack_h2(W[(size_t)(kbase+0)*H_ + n], W[(size_t)(kbase+1)*H_ + n]);
            o.y = pack_h2(W[(size_t)(kbase+2)*H_ + n], W[(size_t)(kbase+3)*H_ + n]);
            o.z = pack_h2(W[(size_t)(kbase+4)*H_ + n], W[(size_t)(kbase+5)*H_ + n]);
            o.w = pack_h2(W[(size_t)(kbase+6)*H_ + n], W[(size_t)(kbase+7)*H_ + n]);
            *(uint4*)&g_Wh[(size_t)i * 4] = o;
        } else if (i < 16384 + 512) {
            const int j  = i - 16384;
            const int n  = j >> 5;
            const int k8 = (j & 31) * 8;
            uint4 o;
            o.x = pack_h2(W3[(size_t)(k8+0)*K_ + n], W3[(size_t)(k8+1)*K_ + n]);
            o.y = pack_h2(W3[(size_t)(k8+2)*K_ + n], W3[(size_t)(k8+3)*K_ + n]);
            o.z = pack_h2(W3[(size_t)(k8+4)*K_ + n], W3[(size_t)(k8+5)*K_ + n]);
            o.w = pack_h2(W3[(size_t)(k8+6)*K_ + n], W3[(size_t)(k8+7)*K_ + n]);
            *(uint4*)&g_Wh3[(size_t)j * 4] = o;
        }
    } else {
        const int row  = (blockIdx.x - 66) * 256 + tid;
        const int lane = tid & 31;
        const bool mk  = (mask[row] != 0);
        const unsigned bal = __ballot_sync(0xffffffffu, mk);
        int base = 0;
        if (lane == 0) base = atomicAdd(&g_cnt, __popc(bal));
        base = __shfl_sync(0xffffffffu, base, 0);
        if (mk) {
            g_rows[base + __popc(bal & ((1u << lane) - 1u))] = row;
        } else {
            const float4 m4 = make_float4(-2500.f, -2500.f, -2500.f, -2500.f);
            float4* gp = (float4*)&g_A[(size_t)row * K_];
            gp[0] = m4; gp[1] = m4; gp[2] = m4; gp[3] = m4;
        }
    }
}

// ---------------------------------------------------------------------------
// Kernel 1: fp16 mma.sync MLP on COMPACTED rows + X fp16 export (unchanged)
// ---------------------------------------------------------------------------
__device__ __forceinline__ void prefetch_chunk(uint32_t sb, int tid,
                                               int layer, int cc, int buf) {
    const uint32_t* src = g_Wh + (size_t)(layer * 4 + cc) * 8192 + tid * 32;
    const uint32_t  dst = sb + (uint32_t)(BC_OFF + buf * BC_ONE + tid * CBSTW) * 4;
    #pragma unroll
    for (int j = 0; j < 8; j++) cpasync16(dst + j * 16, src + j * 4);
}
__device__ __forceinline__ void prefetch_w3(uint32_t sb, int tid) {
    #pragma unroll
    for (int q = 0; q < 2; q++) {
        const int i = tid * 2 + q;
        const int n = i >> 5, kk = i & 31;
        cpasync16(sb + (uint32_t)(W3_OFF + n * W3STW + kk * 4) * 4,
                  g_Wh3 + (size_t)i * 4);
    }
}

__global__ __launch_bounds__(256, 1)
void mlp_softk_kernel(const float* __restrict__ X,
                      const int*   __restrict__ mask,
                      const float* __restrict__ b1,
                      const float* __restrict__ b2)
{
    const int total = g_cnt;
    const int row0  = blockIdx.x * TM;
    if (row0 >= total) return;
    const int nrows = min(TM, total - row0);

    extern __shared__ uint32_t smu[];
    const uint32_t sb = smem_u32(smu);
    int* rid = (int*)(smu + RID_OFF);
    const int tid  = threadIdx.x;
    const int wid  = tid >> 5;
    const int lane = tid & 31;
    const int g    = lane >> 2;
    const int tq   = lane & 3;

    prefetch_chunk(sb, tid, 0, 0, 0);
    CP_COMMIT();

    if (tid < 128) rid[tid] = g_rows[row0 + min(tid, nrows - 1)];
    __syncthreads();

    #pragma unroll 4
    for (int it = 0; it < 32; it++) {
        const int idx = tid + it * 256;
        const int r = idx >> 6, c4 = (idx & 63) * 4;
        const int grow = rid[r];
        const float4 v = __ldg((const float4*)(X + (size_t)grow * H_ + c4));
        uint2 o;
        o.x = pack_h2(v.x, v.y);
        o.y = pack_h2(v.z, v.w);
        *(uint2*)&smu[r * ASTW + (c4 >> 1)] = o;
        *(uint2*)&g_Xh[(size_t)grow * 128 + (c4 >> 1)] = o;
    }

    const int wm = wid & 3;
    const int wn = wid >> 2;

    const int q8 = lane >> 3;
    const int r8 = lane & 7;
    int a_lane_off[2];
    #pragma unroll
    for (int mt = 0; mt < 2; mt++)
        a_lane_off[mt] = (wm * 32 + mt * 16 + (q8 & 1) * 8 + r8) * ASTW + (q8 >> 1) * 4;
    const int b_lane_row = (q8 >> 1) * 8 + r8;
    const int b_lane_kw  = (q8 & 1) * 4;

    #pragma unroll 1
    for (int layer = 0; layer < 2; layer++) {
        const float* bg = layer ? b2 : b1;

        float acc[2][16][4];
        #pragma unroll
        for (int mt = 0; mt < 2; mt++)
            #pragma unroll
            for (int n8 = 0; n8 < 16; n8++)
                #pragma unroll
                for (int i = 0; i < 4; i++) acc[mt][n8][i] = 0.0f;

        #pragma unroll 1
        for (int cc = 0; cc < 4; cc++) {
            CP_WAIT0();
            __syncthreads();

            if (layer == 1 && cc == 3) prefetch_w3(sb, tid);
            else {
                const int nl = (cc == 3) ? 1 : layer;
                const int nc = (cc == 3) ? 0 : cc + 1;
                prefetch_chunk(sb, tid, nl, nc, (cc + 1) & 1);
            }
            CP_COMMIT();

            const uint32_t bbase = sb + (uint32_t)(BC_OFF + (cc & 1) * BC_ONE) * 4;
            #pragma unroll
            for (int ks = 0; ks < 4; ks++) {
                const int kw  = (cc * 64 + ks * 16) >> 1;
                const int klw = ks * 8;
                uint32_t a[2][4];
                #pragma unroll
                for (int mt = 0; mt < 2; mt++)
                    ldsm_x4(a[mt][0], a[mt][1], a[mt][2], a[mt][3],
                            sb + (uint32_t)(a_lane_off[mt] + kw) * 4);
                #pragma unroll
                for (int p = 0; p < 8; p++) {
                    const int nrow = wn * 128 + p * 16 + b_lane_row;
                    uint32_t b0a, b1a, b0b, b1b;
                    ldsm_x4(b0a, b1a, b0b, b1b,
                            bbase + (uint32_t)(nrow * CBSTW + klw + b_lane_kw) * 4);
                    mma16(acc[0][2*p    ], a[0], b0a, b1a);
                    mma16(acc[1][2*p    ], a[1], b0a, b1a);
                    mma16(acc[0][2*p + 1], a[0], b0b, b1b);
                    mma16(acc[1][2*p + 1], a[1], b0b, b1b);
                }
            }
        }
        __syncthreads();

        #pragma unroll
        for (int mt = 0; mt < 2; mt++) {
            const int r = wm * 32 + mt * 16 + g;
            #pragma unroll
            for (int n8 = 0; n8 < 16; n8++) {
                const int c = wn * 128 + n8 * 8 + 2 * tq;
                const float2 bb = *(const float2*)&bg[c];
                smu[(r    ) * ASTW + (c >> 1)] =
                    pack_h2(fmaxf(acc[mt][n8][0] + bb.x, 0.f),
                            fmaxf(acc[mt][n8][1] + bb.y, 0.f));
                smu[(r + 8) * ASTW + (c >> 1)] =
                    pack_h2(fmaxf(acc[mt][n8][2] + bb.x, 0.f),
                            fmaxf(acc[mt][n8][3] + bb.y, 0.f));
            }
        }
    }

    CP_WAIT0();
    __syncthreads();

    float acc3[2][4];
    #pragma unroll
    for (int n8 = 0; n8 < 2; n8++)
        #pragma unroll
        for (int i = 0; i < 4; i++) acc3[n8][i] = 0.0f;

    {
        const uint32_t* Bu3 = smu + W3_OFF;
        const int r = wid * 16 + g;
        #pragma unroll 4
        for (int ks = 0; ks < 16; ks++) {
            const int kw = ks * 8;
            uint32_t a[4];
            a[0] = smu[(r    ) * ASTW + kw + tq];
            a[1] = smu[(r + 8) * ASTW + kw + tq];
            a[2] = smu[(r    ) * ASTW + kw + tq + 4];
            a[3] = smu[(r + 8) * ASTW + kw + tq + 4];
            #pragma unroll
            for (int n8 = 0; n8 < 2; n8++) {
                const uint32_t b0 = Bu3[(n8 * 8 + g) * W3STW + kw + tq];
                const uint32_t b1v = Bu3[(n8 * 8 + g) * W3STW + kw + tq + 4];
                mma16(acc3[n8], a, b0, b1v);
            }
        }
    }

    #pragma unroll
    for (int p = 0; p < 2; p++) {
        const int rr  = wid * 16 + g + p * 8;
        const int row = rid[rr];
        float v0 = acc3[0][2 * p], v1 = acc3[0][2 * p + 1];
        float v2 = acc3[1][2 * p], v3 = acc3[1][2 * p + 1];
        float m = fmaxf(fmaxf(v0, v1), fmaxf(v2, v3));
        m = fmaxf(m, __shfl_xor_sync(0xffffffffu, m, 1));
        m = fmaxf(m, __shfl_xor_sync(0xffffffffu, m, 2));
        const float e0 = expf(v0 - m), e1 = expf(v1 - m);
        const float e2 = expf(v2 - m), e3 = expf(v3 - m);
        float ssum = e0 + e1 + e2 + e3;
        ssum += __shfl_xor_sync(0xffffffffu, ssum, 1);
        ssum += __shfl_xor_sync(0xffffffffu, ssum, 2);
        const float inv = 0.25f / ssum;
        const bool mk = (mask[row] != 0);
        float2 oa, ob;
        oa.x = mk ? e0 * inv : -2500.0f;
        oa.y = mk ? e1 * inv : -2500.0f;
        ob.x = mk ? e2 * inv : -2500.0f;
        ob.y = mk ? e3 * inv : -2500.0f;
        *(float2*)&g_A[(size_t)row * K_ + 2 * tq]     = oa;
        *(float2*)&g_A[(size_t)row * K_ + 8 + 2 * tq] = ob;
    }
}

// ---------------------------------------------------------------------------
// Kernel 2: ONE CTA per batch. ALL 4 X chunks prefetched upfront (128KB smem),
// softmax hides the load, then the 16-kstep GEMM runs with ONE wait + barrier.
// ---------------------------------------------------------------------------
__global__ __launch_bounds__(256, 1)
void out_gemm_kernel(const float* __restrict__ tf,
                     float*       __restrict__ out)
{
    extern __shared__ uint32_t smu[];
    const uint32_t sb = smem_u32(smu);
    const int tid  = threadIdx.x;
    const int w    = tid >> 5;          // 0..7
    const int lane = tid & 31;
    const int g    = lane >> 2;
    const int tq   = lane & 3;
    const int b    = blockIdx.x;

    // prefetch ALL X chunks: 256 s-rows x 256 h fp16 = 128KB (8192 lines)
    {
        const uint32_t* src = g_Xh + (size_t)(b * S_) * 128;
        #pragma unroll
        for (int j = 0; j < 32; j++) {
            const int line = tid + j * 256;
            const int r = line >> 5, lw = line & 31;   // r in 0..255
            const int c = r >> 6, rc = r & 63;
            cpasync16(sb + (uint32_t)(c * XBUF2 + rc * XSTW2 + lw * 4) * 4,
                      src + (size_t)r * 128 + lw * 4);
        }
        CP_COMMIT();
    }

    float* Af = (float*)(smu + AF2_OFF);
    float* Tf = (float*)(smu + TF2_OFF);
    float* Ik = (float*)(smu + IK2_OFF);

    for (int idx = tid; idx < S_ * K_; idx += 256) {
        const int s = idx >> 4, k = idx & 15;
        Af[s * AFST + k] = g_A[(size_t)b * S_ * K_ + idx];
    }
    for (int idx = tid; idx < S_; idx += 256)
        Tf[idx] = tf[b * S_ + idx];
    __syncthreads();

    // per-k softmax: warp w handles k = w, w+8. exp computed once, stored.
    #pragma unroll
    for (int kk = 0; kk < 2; kk++) {
        const int k = w + kk * 8;
        float m = -1e30f;
        for (int s = lane; s < S_; s += 32) m = fmaxf(m, Af[s * AFST + k]);
        #pragma unroll
        for (int o = 16; o; o >>= 1) m = fmaxf(m, __shfl_xor_sync(0xffffffffu, m, o));
        float ss = 0.0f;
        for (int s = lane; s < S_; s += 32) {
            const float e = expf(Af[s * AFST + k] - m);
            Af[s * AFST + k] = e;
            ss += e;
        }
        #pragma unroll
        for (int o = 16; o; o >>= 1) ss += __shfl_xor_sync(0xffffffffu, ss, o);
        if (lane == 0) Ik[k] = 1.0f / ss;
    }
    __syncthreads();

    // Ds[k][s] fp16 = Af(exp'd) * Ik * Tf  (no MUFU; s padded to 256)
    for (int idx = tid; idx < 16 * 128; idx += 256) {
        const int k = idx >> 7, sw = idx & 127, s0 = sw * 2;
        const float ik = Ik[k];
        float v0 = 0.0f, v1 = 0.0f;
        if (s0     < S_) v0 = Af[s0 * AFST + k]       * ik * Tf[s0];
        if (s0 + 1 < S_) v1 = Af[(s0 + 1) * AFST + k] * ik * Tf[s0 + 1];
        smu[DS2_OFF + k * DST2 + sw] = pack_h2(v0, v1);
    }

    // single wait for all X chunks + Ds visibility
    CP_WAIT0();
    __syncthreads();

    float acc[4][4];
    #pragma unroll
    for (int n8 = 0; n8 < 4; n8++)
        #pragma unroll
        for (int i = 0; i < 4; i++) acc[n8][i] = 0.0f;

    const int q8 = lane >> 3, r8 = lane & 7;
    const int a_off  = DS2_OFF + ((q8 & 1) * 8 + r8) * DST2 + (q8 >> 1) * 4;
    const int b_srow = (q8 & 1) * 8 + r8;
    const int b_hw   = w * 16 + (q8 >> 1) * 4;   // warp w: h words w*16..+15

    // straight-line GEMM: 16 k-steps, no waits
    #pragma unroll 4
    for (int ks = 0; ks < 16; ks++) {
        uint32_t a[4];
        ldsm_x4(a[0], a[1], a[2], a[3],
                sb + (uint32_t)(a_off + ks * 8) * 4);
        const int c  = ks >> 2;
        const int rc = (ks & 3) * 16 + b_srow;   // row within chunk
        #pragma unroll
        for (int p = 0; p < 2; p++) {
            uint32_t r0, r1, r2, r3;
            ldsm_x4_t(r0, r1, r2, r3,
                sb + (uint32_t)(c * XBUF2 + rc * XSTW2 + b_hw + p * 8) * 4);
            mma16(acc[2 * p    ], a, r0, r1);
            mma16(acc[2 * p + 1], a, r2, r3);
        }
    }

    // store out[b][k][h]; warp w covers h = w*32 .. +31
    float* ob = out + (size_t)b * K_ * H_;
    #pragma unroll
    for (int n8 = 0; n8 < 4; n8++) {
        const int h = w * 32 + n8 * 8 + 2 * tq;
        *(float2*)&ob[(g    ) * H_ + h] = make_float2(acc[n8][0], acc[n8][1]);
        *(float2*)&ob[(g + 8) * H_ + h] = make_float2(acc[n8][2], acc[n8][3]);
    }
}

// ---------------------------------------------------------------------------
extern "C" void kernel_launch(void* const* d_in, const int* in_sizes, int n_in,
                              void* d_out, int out_size)
{
    const float* X    = (const float*)d_in[0];   // (B,S,H)
    const int*   mask = (const int*)  d_in[1];   // (B,S,1)
    const float* tf   = (const float*)d_in[2];   // (B,S,1)
    const float* W1   = (const float*)d_in[3];
    const float* b1   = (const float*)d_in[4];
    const float* W2   = (const float*)d_in[5];
    const float* b2   = (const float*)d_in[6];
    const float* W3   = (const float*)d_in[7];
    float* out = (float*)d_out;                  // (B,K,H)

    cudaFuncSetAttribute(mlp_softk_kernel,
                         cudaFuncAttributeMaxDynamicSharedMemorySize, SM_BYTES);
    cudaFuncSetAttribute(out_gemm_kernel,
                         cudaFuncAttributeMaxDynamicSharedMemorySize, K2_BYTES);

    void* cnt_ptr = nullptr;
    cudaGetSymbolAddress(&cnt_ptr, g_cnt);
    cudaMemsetAsync(cnt_ptr, 0, sizeof(int));

    prep_kernel<<<466, 256>>>(W1, W2, W3, mask);
    mlp_softk_kernel<<<NBLK, 256, SM_BYTES>>>(X, mask, b1, b2);
    out_gemm_kernel<<<B_, 256, K2_BYTES>>>(tf, out);
}

// round 14
// speedup vs baseline: 1.1619x; 1.1619x over previous
#include <cuda_runtime.h>
#include <cuda_fp16.h>
#include <math.h>
#include <stdint.h>

#define B_  512
#define S_  200
#define H_  256
#define K_  16
#define ROWS (B_*S_)          // 102400
#define TM  128               // rows per CTA (kernel 1)
#define NBLK (ROWS/TM)        // 800 (max tiles; ~half exit early)

// ---- kernel-1 smem layout (words) ----
#define ASTW  132
#define CBSTW 36
#define A_WORDS  (128*ASTW)
#define BC_OFF   A_WORDS
#define BC_ONE   (256*CBSTW)
#define W3_OFF   (BC_OFF + 2*BC_ONE)
#define W3STW 132
#define RID_OFF  (W3_OFF + 16*W3STW)
#define SM_WORDS (RID_OFF + 128)
#define SM_BYTES (SM_WORDS*4)             // 150272

// ---- gemm kernel smem layout (words): CTA = (batch, h-half) ----
#define GXS   208                         // X s-rows resident (13 k-steps)
#define GXSTW 68                          // X row stride (words); 68%32==4
#define GDS_OFF (GXS*GXSTW)               // 14144 ; Ds: 16 k x 208 s fp16
#define GDST  108                         // Ds row stride; 108%32==12 (ldsm-clean)
#define G_WORDS (GDS_OFF + 16*GDST)       // 15872
#define G_BYTES (G_WORDS*4)               // 63488 -> 3 CTAs/SM

// scratch
__device__ float    g_A[ROWS * K_];          // masked K-softmax logits
__device__ uint32_t g_Xh[(ROWS + 56) * 128]; // X fp16 [row][h]; dead rows stay 0
__device__ uint32_t g_Ds[B_ * 16 * 128];     // Ds fp16 [b][k][s-pair]
__device__ uint32_t g_Wh[2 * 32768];         // W1,W2 fp16 [l][c4][n256][kl64]
__device__ uint32_t g_Wh3[16 * 128];         // W3 fp16 [n16][k256]
__device__ int      g_rows[ROWS];            // compacted unmasked row ids
__device__ int      g_cnt;                   // number of unmasked rows

__device__ __forceinline__ uint32_t smem_u32(const void* p) {
    uint32_t a;
    asm("{ .reg .u64 t; cvta.to.shared.u64 t, %1; cvt.u32.u64 %0, t; }"
        : "=r"(a) : "l"(p));
    return a;
}
__device__ __forceinline__ uint32_t pack_h2(float lo, float hi) {
    const __half2 h = __floats2half2_rn(lo, hi);
    return *(const uint32_t*)&h;
}
__device__ __forceinline__ void mma16(float c[4], const uint32_t a[4],
                                      uint32_t b0, uint32_t b1) {
    asm("mma.sync.aligned.m16n8k16.row.col.f32.f16.f16.f32 "
        "{%0,%1,%2,%3}, {%4,%5,%6,%7}, {%8,%9}, {%0,%1,%2,%3};"
        : "+f"(c[0]), "+f"(c[1]), "+f"(c[2]), "+f"(c[3])
        : "r"(a[0]), "r"(a[1]), "r"(a[2]), "r"(a[3]), "r"(b0), "r"(b1));
}
__device__ __forceinline__ void ldsm_x4(uint32_t& r0, uint32_t& r1,
                                        uint32_t& r2, uint32_t& r3, uint32_t addr) {
    asm volatile("ldmatrix.sync.aligned.m8n8.x4.shared.b16 {%0,%1,%2,%3}, [%4];"
                 : "=r"(r0), "=r"(r1), "=r"(r2), "=r"(r3) : "r"(addr));
}
__device__ __forceinline__ void ldsm_x4_t(uint32_t& r0, uint32_t& r1,
                                          uint32_t& r2, uint32_t& r3, uint32_t addr) {
    asm volatile("ldmatrix.sync.aligned.m8n8.x4.trans.shared.b16 {%0,%1,%2,%3}, [%4];"
                 : "=r"(r0), "=r"(r1), "=r"(r2), "=r"(r3) : "r"(addr));
}
__device__ __forceinline__ void cpasync16(uint32_t dst, const void* src) {
    asm volatile("cp.async.cg.shared.global [%0], [%1], 16;" :: "r"(dst), "l"(src));
}
#define CP_COMMIT() asm volatile("cp.async.commit_group;" ::: "memory")
#define CP_WAIT0()  asm volatile("cp.async.wait_group 0;" ::: "memory")

// ---------------------------------------------------------------------------
// Prep: blocks 0-65 convert weights; blocks 66-465 compact unmasked rows
// ---------------------------------------------------------------------------
__global__ void prep_kernel(const float* __restrict__ W1,
                            const float* __restrict__ W2,
                            const float* __restrict__ W3,
                            const int*   __restrict__ mask)
{
    const int tid = threadIdx.x;
    if (blockIdx.x < 66) {
        const int i = blockIdx.x * 256 + tid;
        if (i < 16384) {
            const int kl8 = i & 7;
            const int n   = (i >> 3) & 255;
            const int c   = (i >> 11) & 3;
            const int l   = i >> 13;
            const float* W = l ? W2 : W1;
            const int kbase = c * 64 + kl8 * 8;
            uint4 o;
            o.x = pack_h2(W[(size_t)(kbase+0)*H_ + n], W[(size_t)(kbase+1)*H_ + n]);
            o.y = pack_h2(W[(size_t)(kbase+2)*H_ + n], W[(size_t)(kbase+3)*H_ + n]);
            o.z = pack_h2(W[(size_t)(kbase+4)*H_ + n], W[(size_t)(kbase+5)*H_ + n]);
            o.w = pack_h2(W[(size_t)(kbase+6)*H_ + n], W[(size_t)(kbase+7)*H_ + n]);
            *(uint4*)&g_Wh[(size_t)i * 4] = o;
        } else if (i < 16384 + 512) {
            const int j  = i - 16384;
            const int n  = j >> 5;
            const int k8 = (j & 31) * 8;
            uint4 o;
            o.x = pack_h2(W3[(size_t)(k8+0)*K_ + n], W3[(size_t)(k8+1)*K_ + n]);
            o.y = pack_h2(W3[(size_t)(k8+2)*K_ + n], W3[(size_t)(k8+3)*K_ + n]);
            o.z = pack_h2(W3[(size_t)(k8+4)*K_ + n], W3[(size_t)(k8+5)*K_ + n]);
            o.w = pack_h2(W3[(size_t)(k8+6)*K_ + n], W3[(size_t)(k8+7)*K_ + n]);
            *(uint4*)&g_Wh3[(size_t)j * 4] = o;
        }
    } else {
        const int row  = (blockIdx.x - 66) * 256 + tid;
        const int lane = tid & 31;
        const bool mk  = (mask[row] != 0);
        const unsigned bal = __ballot_sync(0xffffffffu, mk);
        int base = 0;
        if (lane == 0) base = atomicAdd(&g_cnt, __popc(bal));
        base = __shfl_sync(0xffffffffu, base, 0);
        if (mk) {
            g_rows[base + __popc(bal & ((1u << lane) - 1u))] = row;
        } else {
            const float4 m4 = make_float4(-2500.f, -2500.f, -2500.f, -2500.f);
            float4* gp = (float4*)&g_A[(size_t)row * K_];
            gp[0] = m4; gp[1] = m4; gp[2] = m4; gp[3] = m4;
        }
    }
}

// ---------------------------------------------------------------------------
// Kernel 1: fp16 mma.sync MLP on COMPACTED rows + X fp16 export (round-12)
// ---------------------------------------------------------------------------
__device__ __forceinline__ void prefetch_chunk(uint32_t sb, int tid,
                                               int layer, int cc, int buf) {
    const uint32_t* src = g_Wh + (size_t)(layer * 4 + cc) * 8192 + tid * 32;
    const uint32_t  dst = sb + (uint32_t)(BC_OFF + buf * BC_ONE + tid * CBSTW) * 4;
    #pragma unroll
    for (int j = 0; j < 8; j++) cpasync16(dst + j * 16, src + j * 4);
}
__device__ __forceinline__ void prefetch_w3(uint32_t sb, int tid) {
    #pragma unroll
    for (int q = 0; q < 2; q++) {
        const int i = tid * 2 + q;
        const int n = i >> 5, kk = i & 31;
        cpasync16(sb + (uint32_t)(W3_OFF + n * W3STW + kk * 4) * 4,
                  g_Wh3 + (size_t)i * 4);
    }
}

__global__ __launch_bounds__(256, 1)
void mlp_softk_kernel(const float* __restrict__ X,
                      const int*   __restrict__ mask,
                      const float* __restrict__ b1,
                      const float* __restrict__ b2)
{
    const int total = g_cnt;
    const int row0  = blockIdx.x * TM;
    if (row0 >= total) return;
    const int nrows = min(TM, total - row0);

    extern __shared__ uint32_t smu[];
    const uint32_t sb = smem_u32(smu);
    int* rid = (int*)(smu + RID_OFF);
    const int tid  = threadIdx.x;
    const int wid  = tid >> 5;
    const int lane = tid & 31;
    const int g    = lane >> 2;
    const int tq   = lane & 3;

    prefetch_chunk(sb, tid, 0, 0, 0);
    CP_COMMIT();

    if (tid < 128) rid[tid] = g_rows[row0 + min(tid, nrows - 1)];
    __syncthreads();

    #pragma unroll 4
    for (int it = 0; it < 32; it++) {
        const int idx = tid + it * 256;
        const int r = idx >> 6, c4 = (idx & 63) * 4;
        const int grow = rid[r];
        const float4 v = __ldg((const float4*)(X + (size_t)grow * H_ + c4));
        uint2 o;
        o.x = pack_h2(v.x, v.y);
        o.y = pack_h2(v.z, v.w);
        *(uint2*)&smu[r * ASTW + (c4 >> 1)] = o;
        *(uint2*)&g_Xh[(size_t)grow * 128 + (c4 >> 1)] = o;
    }

    const int wm = wid & 3;
    const int wn = wid >> 2;

    const int q8 = lane >> 3;
    const int r8 = lane & 7;
    int a_lane_off[2];
    #pragma unroll
    for (int mt = 0; mt < 2; mt++)
        a_lane_off[mt] = (wm * 32 + mt * 16 + (q8 & 1) * 8 + r8) * ASTW + (q8 >> 1) * 4;
    const int b_lane_row = (q8 >> 1) * 8 + r8;
    const int b_lane_kw  = (q8 & 1) * 4;

    #pragma unroll 1
    for (int layer = 0; layer < 2; layer++) {
        const float* bg = layer ? b2 : b1;

        float acc[2][16][4];
        #pragma unroll
        for (int mt = 0; mt < 2; mt++)
            #pragma unroll
            for (int n8 = 0; n8 < 16; n8++)
                #pragma unroll
                for (int i = 0; i < 4; i++) acc[mt][n8][i] = 0.0f;

        #pragma unroll 1
        for (int cc = 0; cc < 4; cc++) {
            CP_WAIT0();
            __syncthreads();

            if (layer == 1 && cc == 3) prefetch_w3(sb, tid);
            else {
                const int nl = (cc == 3) ? 1 : layer;
                const int nc = (cc == 3) ? 0 : cc + 1;
                prefetch_chunk(sb, tid, nl, nc, (cc + 1) & 1);
            }
            CP_COMMIT();

            const uint32_t bbase = sb + (uint32_t)(BC_OFF + (cc & 1) * BC_ONE) * 4;
            #pragma unroll
            for (int ks = 0; ks < 4; ks++) {
                const int kw  = (cc * 64 + ks * 16) >> 1;
                const int klw = ks * 8;
                uint32_t a[2][4];
                #pragma unroll
                for (int mt = 0; mt < 2; mt++)
                    ldsm_x4(a[mt][0], a[mt][1], a[mt][2], a[mt][3],
                            sb + (uint32_t)(a_lane_off[mt] + kw) * 4);
                #pragma unroll
                for (int p = 0; p < 8; p++) {
                    const int nrow = wn * 128 + p * 16 + b_lane_row;
                    uint32_t b0a, b1a, b0b, b1b;
                    ldsm_x4(b0a, b1a, b0b, b1b,
                            bbase + (uint32_t)(nrow * CBSTW + klw + b_lane_kw) * 4);
                    mma16(acc[0][2*p    ], a[0], b0a, b1a);
                    mma16(acc[1][2*p    ], a[1], b0a, b1a);
                    mma16(acc[0][2*p + 1], a[0], b0b, b1b);
                    mma16(acc[1][2*p + 1], a[1], b0b, b1b);
                }
            }
        }
        __syncthreads();

        #pragma unroll
        for (int mt = 0; mt < 2; mt++) {
            const int r = wm * 32 + mt * 16 + g;
            #pragma unroll
            for (int n8 = 0; n8 < 16; n8++) {
                const int c = wn * 128 + n8 * 8 + 2 * tq;
                const float2 bb = *(const float2*)&bg[c];
                smu[(r    ) * ASTW + (c >> 1)] =
                    pack_h2(fmaxf(acc[mt][n8][0] + bb.x, 0.f),
                            fmaxf(acc[mt][n8][1] + bb.y, 0.f));
                smu[(r + 8) * ASTW + (c >> 1)] =
                    pack_h2(fmaxf(acc[mt][n8][2] + bb.x, 0.f),
                            fmaxf(acc[mt][n8][3] + bb.y, 0.f));
            }
        }
    }

    CP_WAIT0();
    __syncthreads();

    float acc3[2][4];
    #pragma unroll
    for (int n8 = 0; n8 < 2; n8++)
        #pragma unroll
        for (int i = 0; i < 4; i++) acc3[n8][i] = 0.0f;

    {
        const uint32_t* Bu3 = smu + W3_OFF;
        const int r = wid * 16 + g;
        #pragma unroll 4
        for (int ks = 0; ks < 16; ks++) {
            const int kw = ks * 8;
            uint32_t a[4];
            a[0] = smu[(r    ) * ASTW + kw + tq];
            a[1] = smu[(r + 8) * ASTW + kw + tq];
            a[2] = smu[(r    ) * ASTW + kw + tq + 4];
            a[3] = smu[(r + 8) * ASTW + kw + tq + 4];
            #pragma unroll
            for (int n8 = 0; n8 < 2; n8++) {
                const uint32_t b0 = Bu3[(n8 * 8 + g) * W3STW + kw + tq];
                const uint32_t b1v = Bu3[(n8 * 8 + g) * W3STW + kw + tq + 4];
                mma16(acc3[n8], a, b0, b1v);
            }
        }
    }

    #pragma unroll
    for (int p = 0; p < 2; p++) {
        const int rr  = wid * 16 + g + p * 8;
        const int row = rid[rr];
        float v0 = acc3[0][2 * p], v1 = acc3[0][2 * p + 1];
        float v2 = acc3[1][2 * p], v3 = acc3[1][2 * p + 1];
        float m = fmaxf(fmaxf(v0, v1), fmaxf(v2, v3));
        m = fmaxf(m, __shfl_xor_sync(0xffffffffu, m, 1));
        m = fmaxf(m, __shfl_xor_sync(0xffffffffu, m, 2));
        const float e0 = expf(v0 - m), e1 = expf(v1 - m);
        const float e2 = expf(v2 - m), e3 = expf(v3 - m);
        float ssum = e0 + e1 + e2 + e3;
        ssum += __shfl_xor_sync(0xffffffffu, ssum, 1);
        ssum += __shfl_xor_sync(0xffffffffu, ssum, 2);
        const float inv = 0.25f / ssum;
        const bool mk = (mask[row] != 0);
        float2 oa, ob;
        oa.x = mk ? e0 * inv : -2500.0f;
        oa.y = mk ? e1 * inv : -2500.0f;
        ob.x = mk ? e2 * inv : -2500.0f;
        ob.y = mk ? e3 * inv : -2500.0f;
        *(float2*)&g_A[(size_t)row * K_ + 2 * tq]     = oa;
        *(float2*)&g_A[(size_t)row * K_ + 8 + 2 * tq] = ob;
    }
}

// ---------------------------------------------------------------------------
// Kernel 2a: per-batch S-softmax (single exp) + time factor -> g_Ds fp16
// grid = 512, block = 128 (4 warps; warp w handles k = w, w+4, w+8, w+12)
// ---------------------------------------------------------------------------
__global__ __launch_bounds__(128, 8)
void ds_kernel(const float* __restrict__ tf)
{
    __shared__ float Af[S_ * 17];
    __shared__ float Tf[S_];
    __shared__ float Ik[16];

    const int b    = blockIdx.x;
    const int tid  = threadIdx.x;
    const int w    = tid >> 5;
    const int lane = tid & 31;

    for (int idx = tid; idx < S_ * K_; idx += 128) {
        const int s = idx >> 4, k = idx & 15;
        Af[s * 17 + k] = g_A[(size_t)b * S_ * K_ + idx];
    }
    for (int idx = tid; idx < S_; idx += 128)
        Tf[idx] = tf[b * S_ + idx];
    __syncthreads();

    #pragma unroll
    for (int kk = 0; kk < 4; kk++) {
        const int k = w + kk * 4;
        float m = -1e30f;
        for (int s = lane; s < S_; s += 32) m = fmaxf(m, Af[s * 17 + k]);
        #pragma unroll
        for (int o = 16; o; o >>= 1) m = fmaxf(m, __shfl_xor_sync(0xffffffffu, m, o));
        float ss = 0.0f;
        for (int s = lane; s < S_; s += 32) {
            const float e = expf(Af[s * 17 + k] - m);
            Af[s * 17 + k] = e;
            ss += e;
        }
        #pragma unroll
        for (int o = 16; o; o >>= 1) ss += __shfl_xor_sync(0xffffffffu, ss, o);
        if (lane == 0) Ik[k] = 1.0f / ss;
    }
    __syncthreads();

    // g_Ds[b][k][sw] fp16 pair (s padded to 256 with zeros)
    for (int idx = tid; idx < 16 * 128; idx += 128) {
        const int k = idx >> 7, sw = idx & 127, s0 = sw * 2;
        const float ik = Ik[k];
        float v0 = 0.0f, v1 = 0.0f;
        if (s0     < S_) v0 = Af[s0 * 17 + k]       * ik * Tf[s0];
        if (s0 + 1 < S_) v1 = Af[(s0 + 1) * 17 + k] * ik * Tf[s0 + 1];
        g_Ds[(size_t)b * 2048 + k * 128 + sw] = pack_h2(v0, v1);
    }
}

// ---------------------------------------------------------------------------
// Kernel 2b: output GEMM. grid (512, 2) — CTA = (batch, h-half), 128 thr.
// X (208 s-rows x 128 h) + Ds issued upfront via cp.async, ONE wait, then a
// straight-line 13-kstep 16x128 GEMM. 62KB smem -> 3 CTAs/SM.
// ---------------------------------------------------------------------------
__global__ __launch_bounds__(128, 3)
void out_gemm_kernel(float* __restrict__ out)
{
    extern __shared__ uint32_t smu[];
    const uint32_t sb = smem_u32(smu);
    const int tid  = threadIdx.x;
    const int w    = tid >> 5;          // 0..3
    const int lane = tid & 31;
    const int g    = lane >> 2;
    const int tq   = lane & 3;
    const int b    = blockIdx.x;
    const int hb   = blockIdx.y;        // h-half

    // X: 208 rows x 16 lines (16B) each = 3328 lines
    {
        const uint32_t* src = g_Xh + (size_t)(b * S_) * 128 + hb * 64;
        #pragma unroll
        for (int j = 0; j < 26; j++) {
            const int line = tid + j * 128;
            const int r = line >> 4, lw = line & 15;
            cpasync16(sb + (uint32_t)(r * GXSTW + lw * 4) * 4,
                      src + (size_t)r * 128 + lw * 4);
        }
    }
    // Ds: 16 k x 26 lines = 416 lines
    {
        const uint32_t* src = g_Ds + (size_t)b * 2048;
        #pragma unroll
        for (int j = 0; j < 4; j++) {
            const int idx = tid + j * 128;
            if (idx < 416) {
                const int k = idx / 26, lw = idx % 26;
                cpasync16(sb + (uint32_t)(GDS_OFF + k * GDST + lw * 4) * 4,
                          src + (size_t)k * 128 + lw * 4);
            }
        }
    }
    CP_COMMIT();
    CP_WAIT0();
    __syncthreads();

    float acc[4][4];
    #pragma unroll
    for (int n8 = 0; n8 < 4; n8++)
        #pragma unroll
        for (int i = 0; i < 4; i++) acc[n8][i] = 0.0f;

    const int q8 = lane >> 3, r8 = lane & 7;
    const int a_off  = GDS_OFF + ((q8 & 1) * 8 + r8) * GDST + (q8 >> 1) * 4;
    const int b_srow = (q8 & 1) * 8 + r8;
    const int b_hw   = w * 16 + (q8 >> 1) * 4;   // warp w: local h words

    #pragma unroll 13
    for (int ks = 0; ks < 13; ks++) {
        uint32_t a[4];
        ldsm_x4(a[0], a[1], a[2], a[3], sb + (uint32_t)(a_off + ks * 8) * 4);
        const int rbase = ks * 16 + b_srow;
        #pragma unroll
        for (int p = 0; p < 2; p++) {
            uint32_t r0, r1, r2, r3;
            ldsm_x4_t(r0, r1, r2, r3,
                sb + (uint32_t)(rbase * GXSTW + b_hw + p * 8) * 4);
            mma16(acc[2 * p    ], a, r0, r1);
            mma16(acc[2 * p + 1], a, r2, r3);
        }
    }

    // store out[b][k][hb*128 + local h]; warp w covers local h = w*32 .. +31
    float* ob = out + (size_t)b * K_ * H_ + hb * 128;
    #pragma unroll
    for (int n8 = 0; n8 < 4; n8++) {
        const int h = w * 32 + n8 * 8 + 2 * tq;
        *(float2*)&ob[(g    ) * H_ + h] = make_float2(acc[n8][0], acc[n8][1]);
        *(float2*)&ob[(g + 8) * H_ + h] = make_float2(acc[n8][2], acc[n8][3]);
    }
}

// ---------------------------------------------------------------------------
extern "C" void kernel_launch(void* const* d_in, const int* in_sizes, int n_in,
                              void* d_out, int out_size)
{
    const float* X    = (const float*)d_in[0];   // (B,S,H)
    const int*   mask = (const int*)  d_in[1];   // (B,S,1)
    const float* tf   = (const float*)d_in[2];   // (B,S,1)
    const float* W1   = (const float*)d_in[3];
    const float* b1   = (const float*)d_in[4];
    const float* W2   = (const float*)d_in[5];
    const float* b2   = (const float*)d_in[6];
    const float* W3   = (const float*)d_in[7];
    float* out = (float*)d_out;                  // (B,K,H)

    cudaFuncSetAttribute(mlp_softk_kernel,
                         cudaFuncAttributeMaxDynamicSharedMemorySize, SM_BYTES);
    cudaFuncSetAttribute(out_gemm_kernel,
                         cudaFuncAttributeMaxDynamicSharedMemorySize, G_BYTES);

    void* cnt_ptr = nullptr;
    cudaGetSymbolAddress(&cnt_ptr, g_cnt);
    cudaMemsetAsync(cnt_ptr, 0, sizeof(int));

    prep_kernel<<<466, 256>>>(W1, W2, W3, mask);
    mlp_softk_kernel<<<NBLK, 256, SM_BYTES>>>(X, mask, b1, b2);
    ds_kernel<<<B_, 128>>>(tf);
    out_gemm_kernel<<<dim3(B_, 2), 128, G_BYTES>>>(out);
}

// round 15
// speedup vs baseline: 1.2025x; 1.0349x over previous
#include <cuda_runtime.h>
#include <cuda_fp16.h>
#include <math.h>
#include <stdint.h>

#define B_  512
#define S_  200
#define H_  256
#define K_  16
#define ROWS (B_*S_)          // 102400
#define TM  128               // rows per CTA (kernel 1)
#define NBLK (ROWS/TM)        // 800 (max tiles; ~half exit early)

// ---- kernel-1 smem layout (words) ----
#define ASTW  132
#define CBSTW 36
#define A_WORDS  (128*ASTW)
#define BC_OFF   A_WORDS
#define BC_ONE   (256*CBSTW)
#define W3_OFF   (BC_OFF + 2*BC_ONE)
#define W3STW 132
#define RID_OFF  (W3_OFF + 16*W3STW)
#define SM_WORDS (RID_OFF + 128)
#define SM_BYTES (SM_WORDS*4)             // 150272

// ---- gemm kernel smem layout (words): CTA = (batch, h-half) ----
#define GXS   208                         // X s-rows resident (13 k-steps)
#define GXSTW 68                          // X row stride (words); 68%32==4
#define GDS_OFF (GXS*GXSTW)               // 14144 ; Ds: 16 k x 208 s fp16
#define GDST  108                         // Ds row stride; ldsm-clean
#define G_WORDS (GDS_OFF + 16*GDST)       // 15872
#define G_BYTES (G_WORDS*4)               // 63488 -> 3 CTAs/SM

// scratch
__device__ float    g_A[ROWS * K_];          // masked K-softmax logits
__device__ uint32_t g_Xh[(ROWS + 56) * 128]; // X fp16 [row][h]; dead rows stay 0
__device__ uint32_t g_Ds[B_ * 16 * 128];     // Ds fp16 [b][k][s-pair]
__device__ uint32_t g_Wh[2 * 32768];         // W1,W2 fp16 [l][c4][n256][kl64]
__device__ uint32_t g_Wh3[16 * 128];         // W3 fp16 [n16][k256]
__device__ int      g_rows[ROWS];            // compacted unmasked row ids
__device__ int      g_cnt;                   // number of unmasked rows

__device__ __forceinline__ uint32_t smem_u32(const void* p) {
    uint32_t a;
    asm("{ .reg .u64 t; cvta.to.shared.u64 t, %1; cvt.u32.u64 %0, t; }"
        : "=r"(a) : "l"(p));
    return a;
}
__device__ __forceinline__ uint32_t pack_h2(float lo, float hi) {
    const __half2 h = __floats2half2_rn(lo, hi);
    return *(const uint32_t*)&h;
}
__device__ __forceinline__ void mma16(float c[4], const uint32_t a[4],
                                      uint32_t b0, uint32_t b1) {
    asm("mma.sync.aligned.m16n8k16.row.col.f32.f16.f16.f32 "
        "{%0,%1,%2,%3}, {%4,%5,%6,%7}, {%8,%9}, {%0,%1,%2,%3};"
        : "+f"(c[0]), "+f"(c[1]), "+f"(c[2]), "+f"(c[3])
        : "r"(a[0]), "r"(a[1]), "r"(a[2]), "r"(a[3]), "r"(b0), "r"(b1));
}
__device__ __forceinline__ void ldsm_x4(uint32_t& r0, uint32_t& r1,
                                        uint32_t& r2, uint32_t& r3, uint32_t addr) {
    asm volatile("ldmatrix.sync.aligned.m8n8.x4.shared.b16 {%0,%1,%2,%3}, [%4];"
                 : "=r"(r0), "=r"(r1), "=r"(r2), "=r"(r3) : "r"(addr));
}
__device__ __forceinline__ void ldsm_x4_t(uint32_t& r0, uint32_t& r1,
                                          uint32_t& r2, uint32_t& r3, uint32_t addr) {
    asm volatile("ldmatrix.sync.aligned.m8n8.x4.trans.shared.b16 {%0,%1,%2,%3}, [%4];"
                 : "=r"(r0), "=r"(r1), "=r"(r2), "=r"(r3) : "r"(addr));
}
__device__ __forceinline__ void cpasync16(uint32_t dst, const void* src) {
    asm volatile("cp.async.cg.shared.global [%0], [%1], 16;" :: "r"(dst), "l"(src));
}
#define CP_COMMIT() asm volatile("cp.async.commit_group;" ::: "memory")
#define CP_WAIT0()  asm volatile("cp.async.wait_group 0;" ::: "memory")

// ---------------------------------------------------------------------------
// Prep (coalesced transpose version):
//   blocks 0-31 : W1/W2 64x64 tiles  (b: l = b>>4, c = (b>>2)&3, nt = b&3)
//   block 32    : W3
//   blocks 33+  : row compaction (400 blocks)
// ---------------------------------------------------------------------------
__global__ void prep_kernel(const float* __restrict__ W1,
                            const float* __restrict__ W2,
                            const float* __restrict__ W3,
                            const int*   __restrict__ mask)
{
    __shared__ float ws[4480];            // max(64*65, 256*17) = 4352, padded
    const int tid = threadIdx.x;

    if (blockIdx.x < 32) {
        const int l  = blockIdx.x >> 4;
        const int c  = (blockIdx.x >> 2) & 3;
        const int nt = blockIdx.x & 3;
        const float* W = l ? W2 : W1;
        // coalesced load: 64 k-rows x 64 n-cols -> ws[r][col], stride 65
        #pragma unroll
        for (int j = 0; j < 16; j++) {
            const int idx = tid + j * 256;
            const int r = idx >> 6, col = idx & 63;
            ws[r * 65 + col] = W[(size_t)(c * 64 + r) * H_ + nt * 64 + col];
        }
        __syncthreads();
        // coalesced store: out word idx = ((l*4+c)*256 + n)*32 + kl8*4
        #pragma unroll
        for (int j = 0; j < 2; j++) {
            const int o = tid + j * 256;        // 0..511
            const int nl  = o >> 3;             // local n 0..63
            const int kl8 = o & 7;              // kl group
            uint4 v;
            v.x = pack_h2(ws[(kl8*8+0)*65 + nl], ws[(kl8*8+1)*65 + nl]);
            v.y = pack_h2(ws[(kl8*8+2)*65 + nl], ws[(kl8*8+3)*65 + nl]);
            v.z = pack_h2(ws[(kl8*8+4)*65 + nl], ws[(kl8*8+5)*65 + nl]);
            v.w = pack_h2(ws[(kl8*8+6)*65 + nl], ws[(kl8*8+7)*65 + nl]);
            *(uint4*)&g_Wh[(size_t)(((l*4 + c) * 256 + nt*64 + nl) * 32 + kl8*4)] = v;
        }
    } else if (blockIdx.x == 32) {
        // W3: 256 k x 16 n -> g_Wh3[n][k]
        #pragma unroll
        for (int j = 0; j < 16; j++) {
            const int idx = tid + j * 256;
            const int k = idx >> 4, n = idx & 15;
            ws[k * 17 + n] = W3[idx];
        }
        __syncthreads();
        #pragma unroll
        for (int j = 0; j < 2; j++) {
            const int o = tid + j * 256;        // 0..511
            const int n   = o >> 5;             // 0..15
            const int kw8 = o & 31;             // uint4 covers k = kw8*8..+7
            uint4 v;
            v.x = pack_h2(ws[(kw8*8+0)*17 + n], ws[(kw8*8+1)*17 + n]);
            v.y = pack_h2(ws[(kw8*8+2)*17 + n], ws[(kw8*8+3)*17 + n]);
            v.z = pack_h2(ws[(kw8*8+4)*17 + n], ws[(kw8*8+5)*17 + n]);
            v.w = pack_h2(ws[(kw8*8+6)*17 + n], ws[(kw8*8+7)*17 + n]);
            *(uint4*)&g_Wh3[(size_t)(n * 128 + kw8 * 4)] = v;
        }
    } else {
        const int row  = (blockIdx.x - 33) * 256 + tid;
        const int lane = tid & 31;
        const bool mk  = (mask[row] != 0);
        const unsigned bal = __ballot_sync(0xffffffffu, mk);
        int base = 0;
        if (lane == 0) base = atomicAdd(&g_cnt, __popc(bal));
        base = __shfl_sync(0xffffffffu, base, 0);
        if (mk) {
            g_rows[base + __popc(bal & ((1u << lane) - 1u))] = row;
        } else {
            const float4 m4 = make_float4(-2500.f, -2500.f, -2500.f, -2500.f);
            float4* gp = (float4*)&g_A[(size_t)row * K_];
            gp[0] = m4; gp[1] = m4; gp[2] = m4; gp[3] = m4;
        }
    }
}

// ---------------------------------------------------------------------------
// Kernel 1: fp16 mma.sync MLP on COMPACTED rows + X fp16 export (round-12)
// ---------------------------------------------------------------------------
__device__ __forceinline__ void prefetch_chunk(uint32_t sb, int tid,
                                               int layer, int cc, int buf) {
    const uint32_t* src = g_Wh + (size_t)(layer * 4 + cc) * 8192 + tid * 32;
    const uint32_t  dst = sb + (uint32_t)(BC_OFF + buf * BC_ONE + tid * CBSTW) * 4;
    #pragma unroll
    for (int j = 0; j < 8; j++) cpasync16(dst + j * 16, src + j * 4);
}
__device__ __forceinline__ void prefetch_w3(uint32_t sb, int tid) {
    #pragma unroll
    for (int q = 0; q < 2; q++) {
        const int i = tid * 2 + q;
        const int n = i >> 5, kk = i & 31;
        cpasync16(sb + (uint32_t)(W3_OFF + n * W3STW + kk * 4) * 4,
                  g_Wh3 + (size_t)i * 4);
    }
}

__global__ __launch_bounds__(256, 1)
void mlp_softk_kernel(const float* __restrict__ X,
                      const int*   __restrict__ mask,
                      const float* __restrict__ b1,
                      const float* __restrict__ b2)
{
    const int total = g_cnt;
    const int row0  = blockIdx.x * TM;
    if (row0 >= total) return;
    const int nrows = min(TM, total - row0);

    extern __shared__ uint32_t smu[];
    const uint32_t sb = smem_u32(smu);
    int* rid = (int*)(smu + RID_OFF);
    const int tid  = threadIdx.x;
    const int wid  = tid >> 5;
    const int lane = tid & 31;
    const int g    = lane >> 2;
    const int tq   = lane & 3;

    prefetch_chunk(sb, tid, 0, 0, 0);
    CP_COMMIT();

    if (tid < 128) rid[tid] = g_rows[row0 + min(tid, nrows - 1)];
    __syncthreads();

    #pragma unroll 4
    for (int it = 0; it < 32; it++) {
        const int idx = tid + it * 256;
        const int r = idx >> 6, c4 = (idx & 63) * 4;
        const int grow = rid[r];
        const float4 v = __ldg((const float4*)(X + (size_t)grow * H_ + c4));
        uint2 o;
        o.x = pack_h2(v.x, v.y);
        o.y = pack_h2(v.z, v.w);
        *(uint2*)&smu[r * ASTW + (c4 >> 1)] = o;
        *(uint2*)&g_Xh[(size_t)grow * 128 + (c4 >> 1)] = o;
    }

    const int wm = wid & 3;
    const int wn = wid >> 2;

    const int q8 = lane >> 3;
    const int r8 = lane & 7;
    int a_lane_off[2];
    #pragma unroll
    for (int mt = 0; mt < 2; mt++)
        a_lane_off[mt] = (wm * 32 + mt * 16 + (q8 & 1) * 8 + r8) * ASTW + (q8 >> 1) * 4;
    const int b_lane_row = (q8 >> 1) * 8 + r8;
    const int b_lane_kw  = (q8 & 1) * 4;

    #pragma unroll 1
    for (int layer = 0; layer < 2; layer++) {
        const float* bg = layer ? b2 : b1;

        float acc[2][16][4];
        #pragma unroll
        for (int mt = 0; mt < 2; mt++)
            #pragma unroll
            for (int n8 = 0; n8 < 16; n8++)
                #pragma unroll
                for (int i = 0; i < 4; i++) acc[mt][n8][i] = 0.0f;

        #pragma unroll 1
        for (int cc = 0; cc < 4; cc++) {
            CP_WAIT0();
            __syncthreads();

            if (layer == 1 && cc == 3) prefetch_w3(sb, tid);
            else {
                const int nl = (cc == 3) ? 1 : layer;
                const int nc = (cc == 3) ? 0 : cc + 1;
                prefetch_chunk(sb, tid, nl, nc, (cc + 1) & 1);
            }
            CP_COMMIT();

            const uint32_t bbase = sb + (uint32_t)(BC_OFF + (cc & 1) * BC_ONE) * 4;
            #pragma unroll
            for (int ks = 0; ks < 4; ks++) {
                const int kw  = (cc * 64 + ks * 16) >> 1;
                const int klw = ks * 8;
                uint32_t a[2][4];
                #pragma unroll
                for (int mt = 0; mt < 2; mt++)
                    ldsm_x4(a[mt][0], a[mt][1], a[mt][2], a[mt][3],
                            sb + (uint32_t)(a_lane_off[mt] + kw) * 4);
                #pragma unroll
                for (int p = 0; p < 8; p++) {
                    const int nrow = wn * 128 + p * 16 + b_lane_row;
                    uint32_t b0a, b1a, b0b, b1b;
                    ldsm_x4(b0a, b1a, b0b, b1b,
                            bbase + (uint32_t)(nrow * CBSTW + klw + b_lane_kw) * 4);
                    mma16(acc[0][2*p    ], a[0], b0a, b1a);
                    mma16(acc[1][2*p    ], a[1], b0a, b1a);
                    mma16(acc[0][2*p + 1], a[0], b0b, b1b);
                    mma16(acc[1][2*p + 1], a[1], b0b, b1b);
                }
            }
        }
        __syncthreads();

        #pragma unroll
        for (int mt = 0; mt < 2; mt++) {
            const int r = wm * 32 + mt * 16 + g;
            #pragma unroll
            for (int n8 = 0; n8 < 16; n8++) {
                const int c = wn * 128 + n8 * 8 + 2 * tq;
                const float2 bb = *(const float2*)&bg[c];
                smu[(r    ) * ASTW + (c >> 1)] =
                    pack_h2(fmaxf(acc[mt][n8][0] + bb.x, 0.f),
                            fmaxf(acc[mt][n8][1] + bb.y, 0.f));
                smu[(r + 8) * ASTW + (c >> 1)] =
                    pack_h2(fmaxf(acc[mt][n8][2] + bb.x, 0.f),
                            fmaxf(acc[mt][n8][3] + bb.y, 0.f));
            }
        }
    }

    CP_WAIT0();
    __syncthreads();

    float acc3[2][4];
    #pragma unroll
    for (int n8 = 0; n8 < 2; n8++)
        #pragma unroll
        for (int i = 0; i < 4; i++) acc3[n8][i] = 0.0f;

    {
        const uint32_t* Bu3 = smu + W3_OFF;
        const int r = wid * 16 + g;
        #pragma unroll 4
        for (int ks = 0; ks < 16; ks++) {
            const int kw = ks * 8;
            uint32_t a[4];
            a[0] = smu[(r    ) * ASTW + kw + tq];
            a[1] = smu[(r + 8) * ASTW + kw + tq];
            a[2] = smu[(r    ) * ASTW + kw + tq + 4];
            a[3] = smu[(r + 8) * ASTW + kw + tq + 4];
            #pragma unroll
            for (int n8 = 0; n8 < 2; n8++) {
                const uint32_t b0 = Bu3[(n8 * 8 + g) * W3STW + kw + tq];
                const uint32_t b1v = Bu3[(n8 * 8 + g) * W3STW + kw + tq + 4];
                mma16(acc3[n8], a, b0, b1v);
            }
        }
    }

    #pragma unroll
    for (int p = 0; p < 2; p++) {
        const int rr  = wid * 16 + g + p * 8;
        const int row = rid[rr];
        float v0 = acc3[0][2 * p], v1 = acc3[0][2 * p + 1];
        float v2 = acc3[1][2 * p], v3 = acc3[1][2 * p + 1];
        float m = fmaxf(fmaxf(v0, v1), fmaxf(v2, v3));
        m = fmaxf(m, __shfl_xor_sync(0xffffffffu, m, 1));
        m = fmaxf(m, __shfl_xor_sync(0xffffffffu, m, 2));
        const float e0 = expf(v0 - m), e1 = expf(v1 - m);
        const float e2 = expf(v2 - m), e3 = expf(v3 - m);
        float ssum = e0 + e1 + e2 + e3;
        ssum += __shfl_xor_sync(0xffffffffu, ssum, 1);
        ssum += __shfl_xor_sync(0xffffffffu, ssum, 2);
        const float inv = 0.25f / ssum;
        const bool mk = (mask[row] != 0);
        float2 oa, ob;
        oa.x = mk ? e0 * inv : -2500.0f;
        oa.y = mk ? e1 * inv : -2500.0f;
        ob.x = mk ? e2 * inv : -2500.0f;
        ob.y = mk ? e3 * inv : -2500.0f;
        *(float2*)&g_A[(size_t)row * K_ + 2 * tq]     = oa;
        *(float2*)&g_A[(size_t)row * K_ + 8 + 2 * tq] = ob;
    }
}

// ---------------------------------------------------------------------------
// Kernel 2a: per-batch S-softmax (single exp) + time factor -> g_Ds fp16
// ---------------------------------------------------------------------------
__global__ __launch_bounds__(128, 8)
void ds_kernel(const float* __restrict__ tf)
{
    __shared__ float Af[S_ * 17];
    __shared__ float Tf[S_];
    __shared__ float Ik[16];

    const int b    = blockIdx.x;
    const int tid  = threadIdx.x;
    const int w    = tid >> 5;
    const int lane = tid & 31;

    for (int idx = tid; idx < S_ * K_; idx += 128) {
        const int s = idx >> 4, k = idx & 15;
        Af[s * 17 + k] = g_A[(size_t)b * S_ * K_ + idx];
    }
    for (int idx = tid; idx < S_; idx += 128)
        Tf[idx] = tf[b * S_ + idx];
    __syncthreads();

    #pragma unroll
    for (int kk = 0; kk < 4; kk++) {
        const int k = w + kk * 4;
        float m = -1e30f;
        for (int s = lane; s < S_; s += 32) m = fmaxf(m, Af[s * 17 + k]);
        #pragma unroll
        for (int o = 16; o; o >>= 1) m = fmaxf(m, __shfl_xor_sync(0xffffffffu, m, o));
        float ss = 0.0f;
        for (int s = lane; s < S_; s += 32) {
            const float e = expf(Af[s * 17 + k] - m);
            Af[s * 17 + k] = e;
            ss += e;
        }
        #pragma unroll
        for (int o = 16; o; o >>= 1) ss += __shfl_xor_sync(0xffffffffu, ss, o);
        if (lane == 0) Ik[k] = 1.0f / ss;
    }
    __syncthreads();

    for (int idx = tid; idx < 16 * 128; idx += 128) {
        const int k = idx >> 7, sw = idx & 127, s0 = sw * 2;
        const float ik = Ik[k];
        float v0 = 0.0f, v1 = 0.0f;
        if (s0     < S_) v0 = Af[s0 * 17 + k]       * ik * Tf[s0];
        if (s0 + 1 < S_) v1 = Af[(s0 + 1) * 17 + k] * ik * Tf[s0 + 1];
        g_Ds[(size_t)b * 2048 + k * 128 + sw] = pack_h2(v0, v1);
    }
}

// ---------------------------------------------------------------------------
// Kernel 2b: output GEMM. grid (512, 2), 128 thr. Masked X rows are NOT
// loaded (Ds==0 exactly there) — smem zero-filled instead. ~halves DRAM.
// ---------------------------------------------------------------------------
__global__ __launch_bounds__(128, 3)
void out_gemm_kernel(const int* __restrict__ mask,
                     float*     __restrict__ out)
{
    extern __shared__ uint32_t smu[];
    const uint32_t sb = smem_u32(smu);
    const int tid  = threadIdx.x;
    const int w    = tid >> 5;          // 0..3
    const int lane = tid & 31;
    const int g    = lane >> 2;
    const int tq   = lane & 3;
    const int b    = blockIdx.x;
    const int hb   = blockIdx.y;        // h-half

    // X: 208 rows x 16 lines (16B). Load only live rows; zero-fill the rest.
    {
        const uint32_t* src = g_Xh + (size_t)(b * S_) * 128 + hb * 64;
        const uint4 z = make_uint4(0u, 0u, 0u, 0u);
        #pragma unroll
        for (int j = 0; j < 26; j++) {
            const int line = tid + j * 128;
            const int r = line >> 4, lw = line & 15;
            const bool live = (r < S_) && (mask[b * S_ + min(r, S_ - 1)] != 0);
            const uint32_t dst = sb + (uint32_t)(r * GXSTW + lw * 4) * 4;
            if (live) cpasync16(dst, src + (size_t)r * 128 + lw * 4);
            else      *(uint4*)(smu + (r * GXSTW + lw * 4)) = z;
        }
    }
    // Ds: 16 k x 26 lines = 416 lines
    {
        const uint32_t* src = g_Ds + (size_t)b * 2048;
        #pragma unroll
        for (int j = 0; j < 4; j++) {
            const int idx = tid + j * 128;
            if (idx < 416) {
                const int k = idx / 26, lw = idx % 26;
                cpasync16(sb + (uint32_t)(GDS_OFF + k * GDST + lw * 4) * 4,
                          src + (size_t)k * 128 + lw * 4);
            }
        }
    }
    CP_COMMIT();
    CP_WAIT0();
    __syncthreads();

    float acc[4][4];
    #pragma unroll
    for (int n8 = 0; n8 < 4; n8++)
        #pragma unroll
        for (int i = 0; i < 4; i++) acc[n8][i] = 0.0f;

    const int q8 = lane >> 3, r8 = lane & 7;
    const int a_off  = GDS_OFF + ((q8 & 1) * 8 + r8) * GDST + (q8 >> 1) * 4;
    const int b_srow = (q8 & 1) * 8 + r8;
    const int b_hw   = w * 16 + (q8 >> 1) * 4;

    #pragma unroll 13
    for (int ks = 0; ks < 13; ks++) {
        uint32_t a[4];
        ldsm_x4(a[0], a[1], a[2], a[3], sb + (uint32_t)(a_off + ks * 8) * 4);
        const int rbase = ks * 16 + b_srow;
        #pragma unroll
        for (int p = 0; p < 2; p++) {
            uint32_t r0, r1, r2, r3;
            ldsm_x4_t(r0, r1, r2, r3,
                sb + (uint32_t)(rbase * GXSTW + b_hw + p * 8) * 4);
            mma16(acc[2 * p    ], a, r0, r1);
            mma16(acc[2 * p + 1], a, r2, r3);
        }
    }

    float* ob = out + (size_t)b * K_ * H_ + hb * 128;
    #pragma unroll
    for (int n8 = 0; n8 < 4; n8++) {
        const int h = w * 32 + n8 * 8 + 2 * tq;
        *(float2*)&ob[(g    ) * H_ + h] = make_float2(acc[n8][0], acc[n8][1]);
        *(float2*)&ob[(g + 8) * H_ + h] = make_float2(acc[n8][2], acc[n8][3]);
    }
}

// ---------------------------------------------------------------------------
extern "C" void kernel_launch(void* const* d_in, const int* in_sizes, int n_in,
                              void* d_out, int out_size)
{
    const float* X    = (const float*)d_in[0];   // (B,S,H)
    const int*   mask = (const int*)  d_in[1];   // (B,S,1)
    const float* tf   = (const float*)d_in[2];   // (B,S,1)
    const float* W1   = (const float*)d_in[3];
    const float* b1   = (const float*)d_in[4];
    const float* W2   = (const float*)d_in[5];
    const float* b2   = (const float*)d_in[6];
    const float* W3   = (const float*)d_in[7];
    float* out = (float*)d_out;                  // (B,K,H)

    cudaFuncSetAttribute(mlp_softk_kernel,
                         cudaFuncAttributeMaxDynamicSharedMemorySize, SM_BYTES);
    cudaFuncSetAttribute(out_gemm_kernel,
                         cudaFuncAttributeMaxDynamicSharedMemorySize, G_BYTES);

    void* cnt_ptr = nullptr;
    cudaGetSymbolAddress(&cnt_ptr, g_cnt);
    cudaMemsetAsync(cnt_ptr, 0, sizeof(int));

    prep_kernel<<<433, 256>>>(W1, W2, W3, mask);
    mlp_softk_kernel<<<NBLK, 256, SM_BYTES>>>(X, mask, b1, b2);
    ds_kernel<<<B_, 128>>>(tf);
    out_gemm_kernel<<<dim3(B_, 2), 128, G_BYTES>>>(mask, out);
}

// round 16
// speedup vs baseline: 1.2158x; 1.0111x over previous
#include <cuda_runtime.h>
#include <cuda_fp16.h>
#include <math.h>
#include <stdint.h>

#define B_  512
#define S_  200
#define H_  256
#define K_  16
#define ROWS (B_*S_)          // 102400
#define TM  128               // rows per CTA (kernel 1)
#define NBLK (ROWS/TM)        // 800 (max tiles; ~half exit early)

// ---- kernel-1 smem layout (words) ----
#define ASTW  132
#define CBSTW 36
#define A_WORDS  (128*ASTW)
#define BC_OFF   A_WORDS
#define BC_ONE   (256*CBSTW)
#define W3_OFF   (BC_OFF + 2*BC_ONE)
#define W3STW 132
#define RID_OFF  (W3_OFF + 16*W3STW)
#define SM_WORDS (RID_OFF + 128)
#define SM_BYTES (SM_WORDS*4)             // 150272

// ---- gemm kernel smem layout (words): CTA = (batch, h-quarter) ----
#define GXS   208                         // X s-rows resident (13 k-steps)
#define GXSTW 36                          // X row stride (words); 36%32==4
#define GDS_OFF (GXS*GXSTW)               // 7488 ; Ds: 16 k x 208 s fp16
#define GDST  108                         // Ds row stride; ldsm-clean
#define G_WORDS (GDS_OFF + 16*GDST)       // 9216
#define G_BYTES (G_WORDS*4)               // 36864 -> 6 CTAs/SM

// scratch
__device__ float    g_A[ROWS * K_];          // masked K-softmax logits
__device__ uint32_t g_Xh[(ROWS + 56) * 128]; // X fp16 [row][h]; dead rows stay 0
__device__ uint32_t g_Ds[B_ * 16 * 128];     // Ds fp16 [b][k][s-pair]
__device__ uint32_t g_Wh[2 * 32768];         // W1,W2 fp16 [l][c4][n256][kl64]
__device__ uint32_t g_Wh3[16 * 128];         // W3 fp16 [n16][k256]
__device__ int      g_rows[ROWS];            // compacted unmasked row ids
__device__ int      g_cnt;                   // number of unmasked rows

__device__ __forceinline__ uint32_t smem_u32(const void* p) {
    uint32_t a;
    asm("{ .reg .u64 t; cvta.to.shared.u64 t, %1; cvt.u32.u64 %0, t; }"
        : "=r"(a) : "l"(p));
    return a;
}
__device__ __forceinline__ uint32_t pack_h2(float lo, float hi) {
    const __half2 h = __floats2half2_rn(lo, hi);
    return *(const uint32_t*)&h;
}
__device__ __forceinline__ void mma16(float c[4], const uint32_t a[4],
                                      uint32_t b0, uint32_t b1) {
    asm("mma.sync.aligned.m16n8k16.row.col.f32.f16.f16.f32 "
        "{%0,%1,%2,%3}, {%4,%5,%6,%7}, {%8,%9}, {%0,%1,%2,%3};"
        : "+f"(c[0]), "+f"(c[1]), "+f"(c[2]), "+f"(c[3])
        : "r"(a[0]), "r"(a[1]), "r"(a[2]), "r"(a[3]), "r"(b0), "r"(b1));
}
__device__ __forceinline__ void ldsm_x4(uint32_t& r0, uint32_t& r1,
                                        uint32_t& r2, uint32_t& r3, uint32_t addr) {
    asm volatile("ldmatrix.sync.aligned.m8n8.x4.shared.b16 {%0,%1,%2,%3}, [%4];"
                 : "=r"(r0), "=r"(r1), "=r"(r2), "=r"(r3) : "r"(addr));
}
__device__ __forceinline__ void ldsm_x4_t(uint32_t& r0, uint32_t& r1,
                                          uint32_t& r2, uint32_t& r3, uint32_t addr) {
    asm volatile("ldmatrix.sync.aligned.m8n8.x4.trans.shared.b16 {%0,%1,%2,%3}, [%4];"
                 : "=r"(r0), "=r"(r1), "=r"(r2), "=r"(r3) : "r"(addr));
}
__device__ __forceinline__ void cpasync16(uint32_t dst, const void* src) {
    asm volatile("cp.async.cg.shared.global [%0], [%1], 16;" :: "r"(dst), "l"(src));
}
#define CP_COMMIT() asm volatile("cp.async.commit_group;" ::: "memory")
#define CP_WAIT0()  asm volatile("cp.async.wait_group 0;" ::: "memory")

// ---------------------------------------------------------------------------
// Prep (coalesced transpose, round-15):
//   blocks 0-31 : W1/W2 64x64 tiles; block 32: W3; blocks 33+: compaction
// ---------------------------------------------------------------------------
__global__ void prep_kernel(const float* __restrict__ W1,
                            const float* __restrict__ W2,
                            const float* __restrict__ W3,
                            const int*   __restrict__ mask)
{
    __shared__ float ws[4480];
    const int tid = threadIdx.x;

    if (blockIdx.x < 32) {
        const int l  = blockIdx.x >> 4;
        const int c  = (blockIdx.x >> 2) & 3;
        const int nt = blockIdx.x & 3;
        const float* W = l ? W2 : W1;
        #pragma unroll
        for (int j = 0; j < 16; j++) {
            const int idx = tid + j * 256;
            const int r = idx >> 6, col = idx & 63;
            ws[r * 65 + col] = W[(size_t)(c * 64 + r) * H_ + nt * 64 + col];
        }
        __syncthreads();
        #pragma unroll
        for (int j = 0; j < 2; j++) {
            const int o = tid + j * 256;
            const int nl  = o >> 3;
            const int kl8 = o & 7;
            uint4 v;
            v.x = pack_h2(ws[(kl8*8+0)*65 + nl], ws[(kl8*8+1)*65 + nl]);
            v.y = pack_h2(ws[(kl8*8+2)*65 + nl], ws[(kl8*8+3)*65 + nl]);
            v.z = pack_h2(ws[(kl8*8+4)*65 + nl], ws[(kl8*8+5)*65 + nl]);
            v.w = pack_h2(ws[(kl8*8+6)*65 + nl], ws[(kl8*8+7)*65 + nl]);
            *(uint4*)&g_Wh[(size_t)(((l*4 + c) * 256 + nt*64 + nl) * 32 + kl8*4)] = v;
        }
    } else if (blockIdx.x == 32) {
        #pragma unroll
        for (int j = 0; j < 16; j++) {
            const int idx = tid + j * 256;
            const int k = idx >> 4, n = idx & 15;
            ws[k * 17 + n] = W3[idx];
        }
        __syncthreads();
        #pragma unroll
        for (int j = 0; j < 2; j++) {
            const int o = tid + j * 256;
            const int n   = o >> 5;
            const int kw8 = o & 31;
            uint4 v;
            v.x = pack_h2(ws[(kw8*8+0)*17 + n], ws[(kw8*8+1)*17 + n]);
            v.y = pack_h2(ws[(kw8*8+2)*17 + n], ws[(kw8*8+3)*17 + n]);
            v.z = pack_h2(ws[(kw8*8+4)*17 + n], ws[(kw8*8+5)*17 + n]);
            v.w = pack_h2(ws[(kw8*8+6)*17 + n], ws[(kw8*8+7)*17 + n]);
            *(uint4*)&g_Wh3[(size_t)(n * 128 + kw8 * 4)] = v;
        }
    } else {
        const int row  = (blockIdx.x - 33) * 256 + tid;
        const int lane = tid & 31;
        const bool mk  = (mask[row] != 0);
        const unsigned bal = __ballot_sync(0xffffffffu, mk);
        int base = 0;
        if (lane == 0) base = atomicAdd(&g_cnt, __popc(bal));
        base = __shfl_sync(0xffffffffu, base, 0);
        if (mk) {
            g_rows[base + __popc(bal & ((1u << lane) - 1u))] = row;
        } else {
            const float4 m4 = make_float4(-2500.f, -2500.f, -2500.f, -2500.f);
            float4* gp = (float4*)&g_A[(size_t)row * K_];
            gp[0] = m4; gp[1] = m4; gp[2] = m4; gp[3] = m4;
        }
    }
}

// ---------------------------------------------------------------------------
// Kernel 1: fp16 mma.sync MLP on COMPACTED rows + X fp16 export (round-12)
// ---------------------------------------------------------------------------
__device__ __forceinline__ void prefetch_chunk(uint32_t sb, int tid,
                                               int layer, int cc, int buf) {
    const uint32_t* src = g_Wh + (size_t)(layer * 4 + cc) * 8192 + tid * 32;
    const uint32_t  dst = sb + (uint32_t)(BC_OFF + buf * BC_ONE + tid * CBSTW) * 4;
    #pragma unroll
    for (int j = 0; j < 8; j++) cpasync16(dst + j * 16, src + j * 4);
}
__device__ __forceinline__ void prefetch_w3(uint32_t sb, int tid) {
    #pragma unroll
    for (int q = 0; q < 2; q++) {
        const int i = tid * 2 + q;
        const int n = i >> 5, kk = i & 31;
        cpasync16(sb + (uint32_t)(W3_OFF + n * W3STW + kk * 4) * 4,
                  g_Wh3 + (size_t)i * 4);
    }
}

__global__ __launch_bounds__(256, 1)
void mlp_softk_kernel(const float* __restrict__ X,
                      const int*   __restrict__ mask,
                      const float* __restrict__ b1,
                      const float* __restrict__ b2)
{
    const int total = g_cnt;
    const int row0  = blockIdx.x * TM;
    if (row0 >= total) return;
    const int nrows = min(TM, total - row0);

    extern __shared__ uint32_t smu[];
    const uint32_t sb = smem_u32(smu);
    int* rid = (int*)(smu + RID_OFF);
    const int tid  = threadIdx.x;
    const int wid  = tid >> 5;
    const int lane = tid & 31;
    const int g    = lane >> 2;
    const int tq   = lane & 3;

    prefetch_chunk(sb, tid, 0, 0, 0);
    CP_COMMIT();

    if (tid < 128) rid[tid] = g_rows[row0 + min(tid, nrows - 1)];
    __syncthreads();

    #pragma unroll 4
    for (int it = 0; it < 32; it++) {
        const int idx = tid + it * 256;
        const int r = idx >> 6, c4 = (idx & 63) * 4;
        const int grow = rid[r];
        const float4 v = __ldg((const float4*)(X + (size_t)grow * H_ + c4));
        uint2 o;
        o.x = pack_h2(v.x, v.y);
        o.y = pack_h2(v.z, v.w);
        *(uint2*)&smu[r * ASTW + (c4 >> 1)] = o;
        *(uint2*)&g_Xh[(size_t)grow * 128 + (c4 >> 1)] = o;
    }

    const int wm = wid & 3;
    const int wn = wid >> 2;

    const int q8 = lane >> 3;
    const int r8 = lane & 7;
    int a_lane_off[2];
    #pragma unroll
    for (int mt = 0; mt < 2; mt++)
        a_lane_off[mt] = (wm * 32 + mt * 16 + (q8 & 1) * 8 + r8) * ASTW + (q8 >> 1) * 4;
    const int b_lane_row = (q8 >> 1) * 8 + r8;
    const int b_lane_kw  = (q8 & 1) * 4;

    #pragma unroll 1
    for (int layer = 0; layer < 2; layer++) {
        const float* bg = layer ? b2 : b1;

        float acc[2][16][4];
        #pragma unroll
        for (int mt = 0; mt < 2; mt++)
            #pragma unroll
            for (int n8 = 0; n8 < 16; n8++)
                #pragma unroll
                for (int i = 0; i < 4; i++) acc[mt][n8][i] = 0.0f;

        #pragma unroll 1
        for (int cc = 0; cc < 4; cc++) {
            CP_WAIT0();
            __syncthreads();

            if (layer == 1 && cc == 3) prefetch_w3(sb, tid);
            else {
                const int nl = (cc == 3) ? 1 : layer;
                const int nc = (cc == 3) ? 0 : cc + 1;
                prefetch_chunk(sb, tid, nl, nc, (cc + 1) & 1);
            }
            CP_COMMIT();

            const uint32_t bbase = sb + (uint32_t)(BC_OFF + (cc & 1) * BC_ONE) * 4;
            #pragma unroll
            for (int ks = 0; ks < 4; ks++) {
                const int kw  = (cc * 64 + ks * 16) >> 1;
                const int klw = ks * 8;
                uint32_t a[2][4];
                #pragma unroll
                for (int mt = 0; mt < 2; mt++)
                    ldsm_x4(a[mt][0], a[mt][1], a[mt][2], a[mt][3],
                            sb + (uint32_t)(a_lane_off[mt] + kw) * 4);
                #pragma unroll
                for (int p = 0; p < 8; p++) {
                    const int nrow = wn * 128 + p * 16 + b_lane_row;
                    uint32_t b0a, b1a, b0b, b1b;
                    ldsm_x4(b0a, b1a, b0b, b1b,
                            bbase + (uint32_t)(nrow * CBSTW + klw + b_lane_kw) * 4);
                    mma16(acc[0][2*p    ], a[0], b0a, b1a);
                    mma16(acc[1][2*p    ], a[1], b0a, b1a);
                    mma16(acc[0][2*p + 1], a[0], b0b, b1b);
                    mma16(acc[1][2*p + 1], a[1], b0b, b1b);
                }
            }
        }
        __syncthreads();

        #pragma unroll
        for (int mt = 0; mt < 2; mt++) {
            const int r = wm * 32 + mt * 16 + g;
            #pragma unroll
            for (int n8 = 0; n8 < 16; n8++) {
                const int c = wn * 128 + n8 * 8 + 2 * tq;
                const float2 bb = *(const float2*)&bg[c];
                smu[(r    ) * ASTW + (c >> 1)] =
                    pack_h2(fmaxf(acc[mt][n8][0] + bb.x, 0.f),
                            fmaxf(acc[mt][n8][1] + bb.y, 0.f));
                smu[(r + 8) * ASTW + (c >> 1)] =
                    pack_h2(fmaxf(acc[mt][n8][2] + bb.x, 0.f),
                            fmaxf(acc[mt][n8][3] + bb.y, 0.f));
            }
        }
    }

    CP_WAIT0();
    __syncthreads();

    float acc3[2][4];
    #pragma unroll
    for (int n8 = 0; n8 < 2; n8++)
        #pragma unroll
        for (int i = 0; i < 4; i++) acc3[n8][i] = 0.0f;

    {
        const uint32_t* Bu3 = smu + W3_OFF;
        const int r = wid * 16 + g;
        #pragma unroll 4
        for (int ks = 0; ks < 16; ks++) {
            const int kw = ks * 8;
            uint32_t a[4];
            a[0] = smu[(r    ) * ASTW + kw + tq];
            a[1] = smu[(r + 8) * ASTW + kw + tq];
            a[2] = smu[(r    ) * ASTW + kw + tq + 4];
            a[3] = smu[(r + 8) * ASTW + kw + tq + 4];
            #pragma unroll
            for (int n8 = 0; n8 < 2; n8++) {
                const uint32_t b0 = Bu3[(n8 * 8 + g) * W3STW + kw + tq];
                const uint32_t b1v = Bu3[(n8 * 8 + g) * W3STW + kw + tq + 4];
                mma16(acc3[n8], a, b0, b1v);
            }
        }
    }

    #pragma unroll
    for (int p = 0; p < 2; p++) {
        const int rr  = wid * 16 + g + p * 8;
        const int row = rid[rr];
        float v0 = acc3[0][2 * p], v1 = acc3[0][2 * p + 1];
        float v2 = acc3[1][2 * p], v3 = acc3[1][2 * p + 1];
        float m = fmaxf(fmaxf(v0, v1), fmaxf(v2, v3));
        m = fmaxf(m, __shfl_xor_sync(0xffffffffu, m, 1));
        m = fmaxf(m, __shfl_xor_sync(0xffffffffu, m, 2));
        const float e0 = expf(v0 - m), e1 = expf(v1 - m);
        const float e2 = expf(v2 - m), e3 = expf(v3 - m);
        float ssum = e0 + e1 + e2 + e3;
        ssum += __shfl_xor_sync(0xffffffffu, ssum, 1);
        ssum += __shfl_xor_sync(0xffffffffu, ssum, 2);
        const float inv = 0.25f / ssum;
        const bool mk = (mask[row] != 0);
        float2 oa, ob;
        oa.x = mk ? e0 * inv : -2500.0f;
        oa.y = mk ? e1 * inv : -2500.0f;
        ob.x = mk ? e2 * inv : -2500.0f;
        ob.y = mk ? e3 * inv : -2500.0f;
        *(float2*)&g_A[(size_t)row * K_ + 2 * tq]     = oa;
        *(float2*)&g_A[(size_t)row * K_ + 8 + 2 * tq] = ob;
    }
}

// ---------------------------------------------------------------------------
// Kernel 2a: per-batch S-softmax (single exp) + time factor -> g_Ds fp16
// ---------------------------------------------------------------------------
__global__ __launch_bounds__(128, 8)
void ds_kernel(const float* __restrict__ tf)
{
    __shared__ float Af[S_ * 17];
    __shared__ float Tf[S_];
    __shared__ float Ik[16];

    const int b    = blockIdx.x;
    const int tid  = threadIdx.x;
    const int w    = tid >> 5;
    const int lane = tid & 31;

    for (int idx = tid; idx < S_ * K_; idx += 128) {
        const int s = idx >> 4, k = idx & 15;
        Af[s * 17 + k] = g_A[(size_t)b * S_ * K_ + idx];
    }
    for (int idx = tid; idx < S_; idx += 128)
        Tf[idx] = tf[b * S_ + idx];
    __syncthreads();

    #pragma unroll
    for (int kk = 0; kk < 4; kk++) {
        const int k = w + kk * 4;
        float m = -1e30f;
        for (int s = lane; s < S_; s += 32) m = fmaxf(m, Af[s * 17 + k]);
        #pragma unroll
        for (int o = 16; o; o >>= 1) m = fmaxf(m, __shfl_xor_sync(0xffffffffu, m, o));
        float ss = 0.0f;
        for (int s = lane; s < S_; s += 32) {
            const float e = expf(Af[s * 17 + k] - m);
            Af[s * 17 + k] = e;
            ss += e;
        }
        #pragma unroll
        for (int o = 16; o; o >>= 1) ss += __shfl_xor_sync(0xffffffffu, ss, o);
        if (lane == 0) Ik[k] = 1.0f / ss;
    }
    __syncthreads();

    for (int idx = tid; idx < 16 * 128; idx += 128) {
        const int k = idx >> 7, sw = idx & 127, s0 = sw * 2;
        const float ik = Ik[k];
        float v0 = 0.0f, v1 = 0.0f;
        if (s0     < S_) v0 = Af[s0 * 17 + k]       * ik * Tf[s0];
        if (s0 + 1 < S_) v1 = Af[(s0 + 1) * 17 + k] * ik * Tf[s0 + 1];
        g_Ds[(size_t)b * 2048 + k * 128 + sw] = pack_h2(v0, v1);
    }
}

// ---------------------------------------------------------------------------
// Kernel 2b: output GEMM. grid (512, 4) — CTA = (batch, h-quarter), 64 thr
// (2 warps), 36.9KB smem -> 6 CTAs/SM. Masked X rows zero-filled, not loaded.
// ---------------------------------------------------------------------------
__global__ __launch_bounds__(64, 6)
void out_gemm_kernel(const int* __restrict__ mask,
                     float*     __restrict__ out)
{
    extern __shared__ uint32_t smu[];
    const uint32_t sb = smem_u32(smu);
    const int tid  = threadIdx.x;
    const int w    = tid >> 5;          // 0..1
    const int lane = tid & 31;
    const int g    = lane >> 2;
    const int tq   = lane & 3;
    const int b    = blockIdx.x;
    const int hq   = blockIdx.y;        // h-quarter: local 64 h = 32 words

    // X: 208 rows x 8 lines (16B) each = 1664 lines; live rows only.
    {
        const uint32_t* src = g_Xh + (size_t)(b * S_) * 128 + hq * 32;
        const uint4 z = make_uint4(0u, 0u, 0u, 0u);
        #pragma unroll
        for (int j = 0; j < 26; j++) {
            const int line = tid + j * 64;
            const int r = line >> 3, lw = line & 7;
            const bool live = (r < S_) && (mask[b * S_ + min(r, S_ - 1)] != 0);
            const uint32_t dst = sb + (uint32_t)(r * GXSTW + lw * 4) * 4;
            if (live) cpasync16(dst, src + (size_t)r * 128 + lw * 4);
            else      *(uint4*)(smu + (r * GXSTW + lw * 4)) = z;
        }
    }
    // Ds: 16 k x 26 lines = 416 lines
    {
        const uint32_t* src = g_Ds + (size_t)b * 2048;
        #pragma unroll
        for (int j = 0; j < 7; j++) {
            const int idx = tid + j * 64;
            if (idx < 416) {
                const int k = idx / 26, lw = idx % 26;
                cpasync16(sb + (uint32_t)(GDS_OFF + k * GDST + lw * 4) * 4,
                          src + (size_t)k * 128 + lw * 4);
            }
        }
    }
    CP_COMMIT();
    CP_WAIT0();
    __syncthreads();

    float acc[4][4];
    #pragma unroll
    for (int n8 = 0; n8 < 4; n8++)
        #pragma unroll
        for (int i = 0; i < 4; i++) acc[n8][i] = 0.0f;

    const int q8 = lane >> 3, r8 = lane & 7;
    const int a_off  = GDS_OFF + ((q8 & 1) * 8 + r8) * GDST + (q8 >> 1) * 4;
    const int b_srow = (q8 & 1) * 8 + r8;
    const int b_hw   = w * 16 + (q8 >> 1) * 4;   // warp w: local h words

    #pragma unroll 13
    for (int ks = 0; ks < 13; ks++) {
        uint32_t a[4];
        ldsm_x4(a[0], a[1], a[2], a[3], sb + (uint32_t)(a_off + ks * 8) * 4);
        const int rbase = ks * 16 + b_srow;
        #pragma unroll
        for (int p = 0; p < 2; p++) {
            uint32_t r0, r1, r2, r3;
            ldsm_x4_t(r0, r1, r2, r3,
                sb + (uint32_t)(rbase * GXSTW + b_hw + p * 8) * 4);
            mma16(acc[2 * p    ], a, r0, r1);
            mma16(acc[2 * p + 1], a, r2, r3);
        }
    }

    // store out[b][k][hq*64 + local h]; warp w covers local h = w*32 .. +31
    float* ob = out + (size_t)b * K_ * H_ + hq * 64;
    #pragma unroll
    for (int n8 = 0; n8 < 4; n8++) {
        const int h = w * 32 + n8 * 8 + 2 * tq;
        *(float2*)&ob[(g    ) * H_ + h] = make_float2(acc[n8][0], acc[n8][1]);
        *(float2*)&ob[(g + 8) * H_ + h] = make_float2(acc[n8][2], acc[n8][3]);
    }
}

// ---------------------------------------------------------------------------
extern "C" void kernel_launch(void* const* d_in, const int* in_sizes, int n_in,
                              void* d_out, int out_size)
{
    const float* X    = (const float*)d_in[0];   // (B,S,H)
    const int*   mask = (const int*)  d_in[1];   // (B,S,1)
    const float* tf   = (const float*)d_in[2];   // (B,S,1)
    const float* W1   = (const float*)d_in[3];
    const float* b1   = (const float*)d_in[4];
    const float* W2   = (const float*)d_in[5];
    const float* b2   = (const float*)d_in[6];
    const float* W3   = (const float*)d_in[7];
    float* out = (float*)d_out;                  // (B,K,H)

    cudaFuncSetAttribute(mlp_softk_kernel,
                         cudaFuncAttributeMaxDynamicSharedMemorySize, SM_BYTES);
    cudaFuncSetAttribute(out_gemm_kernel,
                         cudaFuncAttributeMaxDynamicSharedMemorySize, G_BYTES);

    void* cnt_ptr = nullptr;
    cudaGetSymbolAddress(&cnt_ptr, g_cnt);
    cudaMemsetAsync(cnt_ptr, 0, sizeof(int));

    prep_kernel<<<433, 256>>>(W1, W2, W3, mask);
    mlp_softk_kernel<<<NBLK, 256, SM_BYTES>>>(X, mask, b1, b2);
    ds_kernel<<<B_, 128>>>(tf);
    out_gemm_kernel<<<dim3(B_, 4), 64, G_BYTES>>>(mask, out);
}